// round 3
// baseline (speedup 1.0000x reference)
#include <cuda_runtime.h>

// ============================================================================
// LocalBranch fused kernel, round 2: fp32 SIMT with packed fma.rn.f32x2
// (Blackwell FFMA2 path, 2x fp32 FMA throughput vs 3-reg FFMA).
// Same fully-fused per-graph-CTA structure as round 1.
// ============================================================================

namespace lb {

using u64 = unsigned long long;

constexpr int TPB   = 512;
constexpr int NODES = 128;
constexpr int IND   = 64;
constexpr int HID   = 256;
constexpr int OUTD  = 128;
constexpr int NBLK  = 3;
constexpr int NG    = 1024;
constexpr int KC    = 16;     // k-chunk for weight staging
constexpr int ZSTR  = 132;    // zT row stride (bank-conflict padding)

constexpr int SX_FLOATS   = NODES * HID;    // 32768
constexpr int SAUX_FLOATS = NODES * ZSTR;   // 16896
constexpr int SW_FLOATS   = KC * HID;       // 4096
constexpr int SMEM_FLOATS = SX_FLOATS + SAUX_FLOATS + SW_FLOATS;
constexpr int SMEM_BYTES  = SMEM_FLOATS * 4;  // 215040 B

__device__ __forceinline__ float warpsum(float v) {
#pragma unroll
    for (int o = 16; o; o >>= 1) v += __shfl_xor_sync(0xffffffffu, v, o);
    return v;
}

// ---- packed f32x2 primitives (SASS FFMA2 path; ptxas won't auto-fuse) ----
__device__ __forceinline__ u64 pack2(float lo, float hi) {
    u64 r;
    asm("mov.b64 %0, {%1, %2};" : "=l"(r) : "f"(lo), "f"(hi));
    return r;
}
__device__ __forceinline__ float2 unpack2(u64 v) {
    float2 r;
    asm("mov.b64 {%0, %1}, %2;" : "=f"(r.x), "=f"(r.y) : "l"(v));
    return r;
}
__device__ __forceinline__ void ffma2(u64& d, u64 a, u64 b) {
    asm("fma.rn.f32x2 %0, %1, %2, %0;" : "+l"(d) : "l"(a), "l"(b));
}
__device__ __forceinline__ u64 addf32x2(u64 a, u64 b) {
    u64 r;
    asm("add.rn.f32x2 %0, %1, %2;" : "=l"(r) : "l"(a), "l"(b));
    return r;
}

// Register-blocked GEMM: C[128, NCOLS] = X[128, KDIM] @ W[KDIM, NCOLS].
// Thread (wid, lane): rows r0..r0+7, packed col pairs starting at c0 = lane*4
// (and c0+128 when NCOLS == 256). Accumulators are f32x2 pairs.
template<int KDIM, int NCOLS>
__device__ __forceinline__ void gemm_tile(
    const float* __restrict__ xin, int xstride,
    const float* __restrict__ Wg,
    float* __restrict__ sw,
    u64 (&acc)[8][4],
    int r0, int c0, int tid)
{
    constexpr int NCH = KDIM / KC;
    constexpr int V4  = (KC * NCOLS) / (TPB * 4);   // float4s per thread
    constexpr int NP  = (NCOLS == 256) ? 4 : 2;     // packed pairs per row

    float4 pre[V4];
    {
        const float4* src = reinterpret_cast<const float4*>(Wg);
#pragma unroll
        for (int q = 0; q < V4; ++q) pre[q] = src[tid * V4 + q];
    }
#pragma unroll
    for (int m = 0; m < 8; ++m)
#pragma unroll
        for (int p = 0; p < NP; ++p) acc[m][p] = 0ull;

#pragma unroll 1
    for (int ch = 0; ch < NCH; ++ch) {
        __syncthreads();   // previous consumers of sw (and sx/saux writers) done
        float4* dst = reinterpret_cast<float4*>(sw);
#pragma unroll
        for (int q = 0; q < V4; ++q) dst[tid * V4 + q] = pre[q];
        __syncthreads();
        if (ch + 1 < NCH) {
            const float4* src =
                reinterpret_cast<const float4*>(Wg + (size_t)(ch + 1) * KC * NCOLS);
#pragma unroll
            for (int q = 0; q < V4; ++q) pre[q] = src[tid * V4 + q];
        }
        const float* xrow = xin + ch * KC;
#pragma unroll 2
        for (int kk = 0; kk < KC; kk += 2) {
            float2 xv[8];
#pragma unroll
            for (int m = 0; m < 8; ++m)
                xv[m] = *reinterpret_cast<const float2*>(
                    &xrow[(r0 + m) * xstride + kk]);
#pragma unroll
            for (int t = 0; t < 2; ++t) {
                ulonglong2 wA = *reinterpret_cast<const ulonglong2*>(
                    &sw[(kk + t) * NCOLS + c0]);
                ulonglong2 wB;
                if constexpr (NCOLS == 256)
                    wB = *reinterpret_cast<const ulonglong2*>(
                        &sw[(kk + t) * NCOLS + c0 + 128]);
#pragma unroll
                for (int m = 0; m < 8; ++m) {
                    float xs = t ? xv[m].y : xv[m].x;
                    u64 xp = pack2(xs, xs);
                    ffma2(acc[m][0], xp, wA.x);
                    ffma2(acc[m][1], xp, wA.y);
                    if constexpr (NCOLS == 256) {
                        ffma2(acc[m][2], xp, wB.x);
                        ffma2(acc[m][3], xp, wB.y);
                    }
                }
            }
        }
    }
}

// LN(+bias) -> relu -> (optional residual) -> write back into sx.
template<bool RES>
__device__ __forceinline__ void epi256(
    u64 (&acc)[8][4], float* __restrict__ sx,
    const float* __restrict__ bias, const float* __restrict__ gamma,
    const float* __restrict__ beta, int r0, int c0)
{
    ulonglong2 bA = *reinterpret_cast<const ulonglong2*>(&bias[c0]);
    ulonglong2 bB = *reinterpret_cast<const ulonglong2*>(&bias[c0 + 128]);
    u64 bp[4] = {bA.x, bA.y, bB.x, bB.y};
    float4 gA = *reinterpret_cast<const float4*>(&gamma[c0]);
    float4 gB = *reinterpret_cast<const float4*>(&gamma[c0 + 128]);
    float4 eA = *reinterpret_cast<const float4*>(&beta[c0]);
    float4 eB = *reinterpret_cast<const float4*>(&beta[c0 + 128]);
    float gv[8] = {gA.x, gA.y, gA.z, gA.w, gB.x, gB.y, gB.z, gB.w};
    float ev[8] = {eA.x, eA.y, eA.z, eA.w, eB.x, eB.y, eB.z, eB.w};
    float mu[8], rs[8];
#pragma unroll
    for (int m = 0; m < 8; ++m) {
        float s1 = 0.f, s2 = 0.f;
#pragma unroll
        for (int p = 0; p < 4; ++p) {
            acc[m][p] = addf32x2(acc[m][p], bp[p]);   // biased value kept packed
            float2 q = unpack2(acc[m][p]);
            s1 += q.x + q.y;
            s2 = fmaf(q.x, q.x, s2);
            s2 = fmaf(q.y, q.y, s2);
        }
        s1 = warpsum(s1);
        s2 = warpsum(s2);
        float m_ = s1 * (1.f / 256.f);
        mu[m] = m_;
        rs[m] = rsqrtf(fmaf(-m_, m_, s2 * (1.f / 256.f)) + 1e-5f);
    }
    __syncthreads();   // all GEMM reads of sx complete before we overwrite
#pragma unroll
    for (int m = 0; m < 8; ++m) {
        float o[8];
#pragma unroll
        for (int p = 0; p < 4; ++p) {
            float2 q = unpack2(acc[m][p]);
            float v0 = fmaf((q.x - mu[m]) * rs[m], gv[2 * p], ev[2 * p]);
            float v1 = fmaf((q.y - mu[m]) * rs[m], gv[2 * p + 1], ev[2 * p + 1]);
            o[2 * p]     = fmaxf(v0, 0.f);
            o[2 * p + 1] = fmaxf(v1, 0.f);
        }
        float* row = &sx[(r0 + m) * HID];
        if (RES) {
            float4 oA = *reinterpret_cast<const float4*>(&row[c0]);
            float4 oB = *reinterpret_cast<const float4*>(&row[c0 + 128]);
            o[0] += oA.x; o[1] += oA.y; o[2] += oA.z; o[3] += oA.w;
            o[4] += oB.x; o[5] += oB.y; o[6] += oB.z; o[7] += oB.w;
        }
        *reinterpret_cast<float4*>(&row[c0]) = make_float4(o[0], o[1], o[2], o[3]);
        *reinterpret_cast<float4*>(&row[c0 + 128]) =
            make_float4(o[4], o[5], o[6], o[7]);
    }
}

__global__ void __launch_bounds__(TPB, 1)
fused_local_branch(const float* __restrict__ H,
                   const float* __restrict__ W_in, const float* __restrict__ b_in,
                   const float* __restrict__ g_in, const float* __restrict__ be_in,
                   const float* __restrict__ Wb, const float* __restrict__ bbias,
                   const float* __restrict__ gb, const float* __restrict__ betab,
                   const float* __restrict__ W_out, const float* __restrict__ b_out,
                   const float* __restrict__ g_out, const float* __restrict__ be_out,
                   float* __restrict__ out)
{
    extern __shared__ float sm[];
    float* sx   = sm;                          // [128][256]
    float* saux = sm + SX_FLOATS;              // H tile, then zT [128][132]
    float* sw   = sm + SX_FLOATS + SAUX_FLOATS;// weight stage / scratch

    const int tid  = threadIdx.x;
    const int lane = tid & 31;
    const int wid  = tid >> 5;
    const int r0   = wid * 8;
    const int c0   = lane * 4;
    const int g    = blockIdx.x;

    // --- load H tile [128,64] into saux ---
    {
        const float4* src =
            reinterpret_cast<const float4*>(H + (size_t)g * NODES * IND);
        float4* dst = reinterpret_cast<float4*>(saux);
#pragma unroll
        for (int q = 0; q < (NODES * IND / 4) / TPB; ++q)
            dst[tid + q * TPB] = src[tid + q * TPB];
    }
    // (gemm_tile's leading __syncthreads orders these STS before use)

    u64 acc[8][4];

    // --- stem: x = relu(LN(H @ W_in + b_in)) ---
    gemm_tile<IND, HID>(saux, IND, W_in, sw, acc, r0, c0, tid);
    epi256<false>(acc, sx, b_in, g_in, be_in, r0, c0);

    // --- residual blocks ---
    for (int blk = 0; blk < NBLK; ++blk) {
        gemm_tile<HID, HID>(sx, HID, Wb + (size_t)blk * HID * HID, sw, acc,
                            r0, c0, tid);
        epi256<true>(acc, sx, bbias + blk * HID, gb + blk * HID,
                     betab + blk * HID, r0, c0);
    }

    // --- head: z = LN(x @ W_out + b_out), stored transposed zT[dim][node] ---
    gemm_tile<HID, OUTD>(sx, HID, W_out, sw, acc, r0, c0, tid);
    {
        ulonglong2 b2 = *reinterpret_cast<const ulonglong2*>(&b_out[c0]);
        u64 bp[2] = {b2.x, b2.y};
        float4 g4 = *reinterpret_cast<const float4*>(&g_out[c0]);
        float4 e4 = *reinterpret_cast<const float4*>(&be_out[c0]);
        float gv[4] = {g4.x, g4.y, g4.z, g4.w};
        float ev[4] = {e4.x, e4.y, e4.z, e4.w};
#pragma unroll
        for (int m = 0; m < 8; ++m) {
            float s1 = 0.f, s2 = 0.f;
            float v[4];
#pragma unroll
            for (int p = 0; p < 2; ++p) {
                acc[m][p] = addf32x2(acc[m][p], bp[p]);
                float2 q = unpack2(acc[m][p]);
                v[2 * p] = q.x; v[2 * p + 1] = q.y;
                s1 += q.x + q.y;
                s2 = fmaf(q.x, q.x, s2);
                s2 = fmaf(q.y, q.y, s2);
            }
            s1 = warpsum(s1);
            s2 = warpsum(s2);
            float mu = s1 * (1.f / 128.f);
            float rs = rsqrtf(fmaf(-mu, mu, s2 * (1.f / 128.f)) + 1e-5f);
#pragma unroll
            for (int n = 0; n < 4; ++n) {
                float z = fmaf((v[n] - mu) * rs, gv[n], ev[n]);
                saux[(c0 + n) * ZSTR + (r0 + m)] = z;   // zT[dim][node]
            }
        }
    }
    __syncthreads();

    // --- squared norms sq[i], zero s accumulator ---
    if (tid < NODES) {
        float s = 0.f;
#pragma unroll 4
        for (int d = 0; d < OUTD; ++d) {
            float v = saux[d * ZSTR + tid];
            s = fmaf(v, v, s);
        }
        sw[tid] = s;                                    // sq
    } else if (tid >= TPB - NODES) {
        sw[NODES + (tid - (TPB - NODES))] = 0.f;        // s sums
    }
    __syncthreads();

    // --- pairwise: thread covers i = c0..c0+3 (lanes), j = r0..r0+7 (warps) ---
    {
        u64 dot2[8][2];
#pragma unroll
        for (int j = 0; j < 8; ++j) { dot2[j][0] = 0ull; dot2[j][1] = 0ull; }

#pragma unroll 2
        for (int d = 0; d < OUTD; ++d) {
            ulonglong2 zi = *reinterpret_cast<const ulonglong2*>(
                &saux[d * ZSTR + c0]);
#pragma unroll
            for (int j = 0; j < 8; ++j) {
                float zj = saux[d * ZSTR + r0 + j];     // broadcast
                u64 zp = pack2(zj, zj);
                ffma2(dot2[j][0], zp, zi.x);
                ffma2(dot2[j][1], zp, zi.y);
            }
        }
        float sqi[4];
#pragma unroll
        for (int n = 0; n < 4; ++n) sqi[n] = sw[c0 + n];
        float sacc[4] = {0.f, 0.f, 0.f, 0.f};
#pragma unroll
        for (int j = 0; j < 8; ++j) {
            float sqj = sw[r0 + j];
            float2 q0 = unpack2(dot2[j][0]);
            float2 q1 = unpack2(dot2[j][1]);
            float dv[4] = {q0.x, q0.y, q1.x, q1.y};
#pragma unroll
            for (int n = 0; n < 4; ++n) {
                float d2 = sqi[n] + sqj - 2.f * dv[n];
                sacc[n] += sqrtf(fmaxf(d2, 0.f) + 1e-12f);
            }
        }
#pragma unroll
        for (int n = 0; n < 4; ++n)
            atomicAdd(&sw[NODES + c0 + n], sacc[n]);
    }
    __syncthreads();

    // --- softmax over 128 logits (warp 0): logits = (ssum/128)/TAU ---
    if (wid == 0) {
        const float scale = 1.f / (128.f * 0.25f);
        float sv[4], mx = -1e30f;
#pragma unroll
        for (int q = 0; q < 4; ++q) {
            sv[q] = sw[NODES + lane + 32 * q] * scale;
            mx = fmaxf(mx, sv[q]);
        }
#pragma unroll
        for (int o = 16; o; o >>= 1)
            mx = fmaxf(mx, __shfl_xor_sync(0xffffffffu, mx, o));
        float e[4], se = 0.f;
#pragma unroll
        for (int q = 0; q < 4; ++q) {
            e[q] = expf(sv[q] - mx);
            se += e[q];
        }
        se = warpsum(se);
        float inv = 1.f / se;
#pragma unroll
        for (int q = 0; q < 4; ++q) {
            float w_ = e[q] * inv;
            int i = lane + 32 * q;
            sw[2 * NODES + i] = w_;
            out[(size_t)NG * OUTD + (size_t)g * NODES + i] = w_;
        }
    }
    __syncthreads();

    // --- v[d] = sum_i w_i * z[i][d] ---
    if (tid < OUTD) {
        float a = 0.f;
#pragma unroll 4
        for (int i = 0; i < NODES; ++i)
            a = fmaf(sw[2 * NODES + i], saux[tid * ZSTR + i], a);
        out[(size_t)g * OUTD + tid] = a;
    }
}

}  // namespace lb

extern "C" void kernel_launch(void* const* d_in, const int* in_sizes, int n_in,
                              void* d_out, int out_size)
{
    (void)in_sizes; (void)n_in; (void)out_size;
    const float* H     = (const float*)d_in[0];
    // d_in[1] = batch_ptr (uniform graphs; unused)
    const float* W_in  = (const float*)d_in[2];
    const float* b_in  = (const float*)d_in[3];
    const float* g_in  = (const float*)d_in[4];
    const float* be_in = (const float*)d_in[5];
    const float* Wb    = (const float*)d_in[6];
    const float* bb    = (const float*)d_in[7];
    const float* gb    = (const float*)d_in[8];
    const float* betab = (const float*)d_in[9];
    const float* W_out = (const float*)d_in[10];
    const float* b_out = (const float*)d_in[11];
    const float* g_out = (const float*)d_in[12];
    const float* be_out= (const float*)d_in[13];
    float* out = (float*)d_out;

    cudaFuncSetAttribute(lb::fused_local_branch,
                         cudaFuncAttributeMaxDynamicSharedMemorySize,
                         lb::SMEM_BYTES);

    lb::fused_local_branch<<<lb::NG, lb::TPB, lb::SMEM_BYTES>>>(
        H, W_in, b_in, g_in, be_in, Wb, bb, gb, betab,
        W_out, b_out, g_out, be_out, out);
}

// round 4
// speedup vs baseline: 1.0566x; 1.0566x over previous
#include <cuda_runtime.h>

// ============================================================================
// LocalBranch fused kernel, round 2: fp32 SIMT with packed fma.rn.f32x2
// (Blackwell FFMA2 path, 2x fp32 FMA throughput vs 3-reg FFMA).
// Same fully-fused per-graph-CTA structure as round 1.
// ============================================================================

namespace lb {

using u64 = unsigned long long;

constexpr int TPB   = 512;
constexpr int NODES = 128;
constexpr int IND   = 64;
constexpr int HID   = 256;
constexpr int OUTD  = 128;
constexpr int NBLK  = 3;
constexpr int NG    = 1024;
constexpr int KC    = 16;     // k-chunk for weight staging
constexpr int ZSTR  = 132;    // zT row stride (bank-conflict padding)

constexpr int SX_FLOATS   = NODES * HID;    // 32768
constexpr int SAUX_FLOATS = NODES * ZSTR;   // 16896
constexpr int SW_FLOATS   = KC * HID;       // 4096
constexpr int SMEM_FLOATS = SX_FLOATS + SAUX_FLOATS + SW_FLOATS;
constexpr int SMEM_BYTES  = SMEM_FLOATS * 4;  // 215040 B

__device__ __forceinline__ float warpsum(float v) {
#pragma unroll
    for (int o = 16; o; o >>= 1) v += __shfl_xor_sync(0xffffffffu, v, o);
    return v;
}

// ---- packed f32x2 primitives (SASS FFMA2 path; ptxas won't auto-fuse) ----
__device__ __forceinline__ u64 pack2(float lo, float hi) {
    u64 r;
    asm("mov.b64 %0, {%1, %2};" : "=l"(r) : "f"(lo), "f"(hi));
    return r;
}
__device__ __forceinline__ float2 unpack2(u64 v) {
    float2 r;
    asm("mov.b64 {%0, %1}, %2;" : "=f"(r.x), "=f"(r.y) : "l"(v));
    return r;
}
__device__ __forceinline__ void ffma2(u64& d, u64 a, u64 b) {
    asm("fma.rn.f32x2 %0, %1, %2, %0;" : "+l"(d) : "l"(a), "l"(b));
}
__device__ __forceinline__ u64 addf32x2(u64 a, u64 b) {
    u64 r;
    asm("add.rn.f32x2 %0, %1, %2;" : "=l"(r) : "l"(a), "l"(b));
    return r;
}

// Register-blocked GEMM: C[128, NCOLS] = X[128, KDIM] @ W[KDIM, NCOLS].
// Thread (wid, lane): rows r0..r0+7, packed col pairs starting at c0 = lane*4
// (and c0+128 when NCOLS == 256). Accumulators are f32x2 pairs.
template<int KDIM, int NCOLS>
__device__ __forceinline__ void gemm_tile(
    const float* __restrict__ xin, int xstride,
    const float* __restrict__ Wg,
    float* __restrict__ sw,
    u64 (&acc)[8][4],
    int r0, int c0, int tid)
{
    constexpr int NCH = KDIM / KC;
    constexpr int V4  = (KC * NCOLS) / (TPB * 4);   // float4s per thread
    constexpr int NP  = (NCOLS == 256) ? 4 : 2;     // packed pairs per row

    float4 pre[V4];
    {
        const float4* src = reinterpret_cast<const float4*>(Wg);
#pragma unroll
        for (int q = 0; q < V4; ++q) pre[q] = src[tid * V4 + q];
    }
#pragma unroll
    for (int m = 0; m < 8; ++m)
#pragma unroll
        for (int p = 0; p < NP; ++p) acc[m][p] = 0ull;

#pragma unroll 1
    for (int ch = 0; ch < NCH; ++ch) {
        __syncthreads();   // previous consumers of sw (and sx/saux writers) done
        float4* dst = reinterpret_cast<float4*>(sw);
#pragma unroll
        for (int q = 0; q < V4; ++q) dst[tid * V4 + q] = pre[q];
        __syncthreads();
        if (ch + 1 < NCH) {
            const float4* src =
                reinterpret_cast<const float4*>(Wg + (size_t)(ch + 1) * KC * NCOLS);
#pragma unroll
            for (int q = 0; q < V4; ++q) pre[q] = src[tid * V4 + q];
        }
        const float* xrow = xin + ch * KC;
#pragma unroll 2
        for (int kk = 0; kk < KC; kk += 2) {
            float2 xv[8];
#pragma unroll
            for (int m = 0; m < 8; ++m)
                xv[m] = *reinterpret_cast<const float2*>(
                    &xrow[(r0 + m) * xstride + kk]);
#pragma unroll
            for (int t = 0; t < 2; ++t) {
                ulonglong2 wA = *reinterpret_cast<const ulonglong2*>(
                    &sw[(kk + t) * NCOLS + c0]);
                ulonglong2 wB;
                if constexpr (NCOLS == 256)
                    wB = *reinterpret_cast<const ulonglong2*>(
                        &sw[(kk + t) * NCOLS + c0 + 128]);
#pragma unroll
                for (int m = 0; m < 8; ++m) {
                    float xs = t ? xv[m].y : xv[m].x;
                    u64 xp = pack2(xs, xs);
                    ffma2(acc[m][0], xp, wA.x);
                    ffma2(acc[m][1], xp, wA.y);
                    if constexpr (NCOLS == 256) {
                        ffma2(acc[m][2], xp, wB.x);
                        ffma2(acc[m][3], xp, wB.y);
                    }
                }
            }
        }
    }
}

// LN(+bias) -> relu -> (optional residual) -> write back into sx.
template<bool RES>
__device__ __forceinline__ void epi256(
    u64 (&acc)[8][4], float* __restrict__ sx,
    const float* __restrict__ bias, const float* __restrict__ gamma,
    const float* __restrict__ beta, int r0, int c0)
{
    ulonglong2 bA = *reinterpret_cast<const ulonglong2*>(&bias[c0]);
    ulonglong2 bB = *reinterpret_cast<const ulonglong2*>(&bias[c0 + 128]);
    u64 bp[4] = {bA.x, bA.y, bB.x, bB.y};
    float4 gA = *reinterpret_cast<const float4*>(&gamma[c0]);
    float4 gB = *reinterpret_cast<const float4*>(&gamma[c0 + 128]);
    float4 eA = *reinterpret_cast<const float4*>(&beta[c0]);
    float4 eB = *reinterpret_cast<const float4*>(&beta[c0 + 128]);
    float gv[8] = {gA.x, gA.y, gA.z, gA.w, gB.x, gB.y, gB.z, gB.w};
    float ev[8] = {eA.x, eA.y, eA.z, eA.w, eB.x, eB.y, eB.z, eB.w};
    float mu[8], rs[8];
#pragma unroll
    for (int m = 0; m < 8; ++m) {
        float s1 = 0.f, s2 = 0.f;
#pragma unroll
        for (int p = 0; p < 4; ++p) {
            acc[m][p] = addf32x2(acc[m][p], bp[p]);   // biased value kept packed
            float2 q = unpack2(acc[m][p]);
            s1 += q.x + q.y;
            s2 = fmaf(q.x, q.x, s2);
            s2 = fmaf(q.y, q.y, s2);
        }
        s1 = warpsum(s1);
        s2 = warpsum(s2);
        float m_ = s1 * (1.f / 256.f);
        mu[m] = m_;
        rs[m] = rsqrtf(fmaf(-m_, m_, s2 * (1.f / 256.f)) + 1e-5f);
    }
    __syncthreads();   // all GEMM reads of sx complete before we overwrite
#pragma unroll
    for (int m = 0; m < 8; ++m) {
        float o[8];
#pragma unroll
        for (int p = 0; p < 4; ++p) {
            float2 q = unpack2(acc[m][p]);
            float v0 = fmaf((q.x - mu[m]) * rs[m], gv[2 * p], ev[2 * p]);
            float v1 = fmaf((q.y - mu[m]) * rs[m], gv[2 * p + 1], ev[2 * p + 1]);
            o[2 * p]     = fmaxf(v0, 0.f);
            o[2 * p + 1] = fmaxf(v1, 0.f);
        }
        float* row = &sx[(r0 + m) * HID];
        if (RES) {
            float4 oA = *reinterpret_cast<const float4*>(&row[c0]);
            float4 oB = *reinterpret_cast<const float4*>(&row[c0 + 128]);
            o[0] += oA.x; o[1] += oA.y; o[2] += oA.z; o[3] += oA.w;
            o[4] += oB.x; o[5] += oB.y; o[6] += oB.z; o[7] += oB.w;
        }
        *reinterpret_cast<float4*>(&row[c0]) = make_float4(o[0], o[1], o[2], o[3]);
        *reinterpret_cast<float4*>(&row[c0 + 128]) =
            make_float4(o[4], o[5], o[6], o[7]);
    }
}

__global__ void __launch_bounds__(TPB, 1)
fused_local_branch(const float* __restrict__ H,
                   const float* __restrict__ W_in, const float* __restrict__ b_in,
                   const float* __restrict__ g_in, const float* __restrict__ be_in,
                   const float* __restrict__ Wb, const float* __restrict__ bbias,
                   const float* __restrict__ gb, const float* __restrict__ betab,
                   const float* __restrict__ W_out, const float* __restrict__ b_out,
                   const float* __restrict__ g_out, const float* __restrict__ be_out,
                   float* __restrict__ out)
{
    extern __shared__ float sm[];
    float* sx   = sm;                          // [128][256]
    float* saux = sm + SX_FLOATS;              // H tile, then zT [128][132]
    float* sw   = sm + SX_FLOATS + SAUX_FLOATS;// weight stage / scratch

    const int tid  = threadIdx.x;
    const int lane = tid & 31;
    const int wid  = tid >> 5;
    const int r0   = wid * 8;
    const int c0   = lane * 4;
    const int g    = blockIdx.x;

    // --- load H tile [128,64] into saux ---
    {
        const float4* src =
            reinterpret_cast<const float4*>(H + (size_t)g * NODES * IND);
        float4* dst = reinterpret_cast<float4*>(saux);
#pragma unroll
        for (int q = 0; q < (NODES * IND / 4) / TPB; ++q)
            dst[tid + q * TPB] = src[tid + q * TPB];
    }
    // (gemm_tile's leading __syncthreads orders these STS before use)

    u64 acc[8][4];

    // --- stem: x = relu(LN(H @ W_in + b_in)) ---
    gemm_tile<IND, HID>(saux, IND, W_in, sw, acc, r0, c0, tid);
    epi256<false>(acc, sx, b_in, g_in, be_in, r0, c0);

    // --- residual blocks ---
    for (int blk = 0; blk < NBLK; ++blk) {
        gemm_tile<HID, HID>(sx, HID, Wb + (size_t)blk * HID * HID, sw, acc,
                            r0, c0, tid);
        epi256<true>(acc, sx, bbias + blk * HID, gb + blk * HID,
                     betab + blk * HID, r0, c0);
    }

    // --- head: z = LN(x @ W_out + b_out), stored transposed zT[dim][node] ---
    gemm_tile<HID, OUTD>(sx, HID, W_out, sw, acc, r0, c0, tid);
    {
        ulonglong2 b2 = *reinterpret_cast<const ulonglong2*>(&b_out[c0]);
        u64 bp[2] = {b2.x, b2.y};
        float4 g4 = *reinterpret_cast<const float4*>(&g_out[c0]);
        float4 e4 = *reinterpret_cast<const float4*>(&be_out[c0]);
        float gv[4] = {g4.x, g4.y, g4.z, g4.w};
        float ev[4] = {e4.x, e4.y, e4.z, e4.w};
#pragma unroll
        for (int m = 0; m < 8; ++m) {
            float s1 = 0.f, s2 = 0.f;
            float v[4];
#pragma unroll
            for (int p = 0; p < 2; ++p) {
                acc[m][p] = addf32x2(acc[m][p], bp[p]);
                float2 q = unpack2(acc[m][p]);
                v[2 * p] = q.x; v[2 * p + 1] = q.y;
                s1 += q.x + q.y;
                s2 = fmaf(q.x, q.x, s2);
                s2 = fmaf(q.y, q.y, s2);
            }
            s1 = warpsum(s1);
            s2 = warpsum(s2);
            float mu = s1 * (1.f / 128.f);
            float rs = rsqrtf(fmaf(-mu, mu, s2 * (1.f / 128.f)) + 1e-5f);
#pragma unroll
            for (int n = 0; n < 4; ++n) {
                float z = fmaf((v[n] - mu) * rs, gv[n], ev[n]);
                saux[(c0 + n) * ZSTR + (r0 + m)] = z;   // zT[dim][node]
            }
        }
    }
    __syncthreads();

    // --- squared norms sq[i], zero s accumulator ---
    if (tid < NODES) {
        float s = 0.f;
#pragma unroll 4
        for (int d = 0; d < OUTD; ++d) {
            float v = saux[d * ZSTR + tid];
            s = fmaf(v, v, s);
        }
        sw[tid] = s;                                    // sq
    } else if (tid >= TPB - NODES) {
        sw[NODES + (tid - (TPB - NODES))] = 0.f;        // s sums
    }
    __syncthreads();

    // --- pairwise: thread covers i = c0..c0+3 (lanes), j = r0..r0+7 (warps) ---
    {
        u64 dot2[8][2];
#pragma unroll
        for (int j = 0; j < 8; ++j) { dot2[j][0] = 0ull; dot2[j][1] = 0ull; }

#pragma unroll 2
        for (int d = 0; d < OUTD; ++d) {
            ulonglong2 zi = *reinterpret_cast<const ulonglong2*>(
                &saux[d * ZSTR + c0]);
#pragma unroll
            for (int j = 0; j < 8; ++j) {
                float zj = saux[d * ZSTR + r0 + j];     // broadcast
                u64 zp = pack2(zj, zj);
                ffma2(dot2[j][0], zp, zi.x);
                ffma2(dot2[j][1], zp, zi.y);
            }
        }
        float sqi[4];
#pragma unroll
        for (int n = 0; n < 4; ++n) sqi[n] = sw[c0 + n];
        float sacc[4] = {0.f, 0.f, 0.f, 0.f};
#pragma unroll
        for (int j = 0; j < 8; ++j) {
            float sqj = sw[r0 + j];
            float2 q0 = unpack2(dot2[j][0]);
            float2 q1 = unpack2(dot2[j][1]);
            float dv[4] = {q0.x, q0.y, q1.x, q1.y};
#pragma unroll
            for (int n = 0; n < 4; ++n) {
                float d2 = sqi[n] + sqj - 2.f * dv[n];
                sacc[n] += sqrtf(fmaxf(d2, 0.f) + 1e-12f);
            }
        }
#pragma unroll
        for (int n = 0; n < 4; ++n)
            atomicAdd(&sw[NODES + c0 + n], sacc[n]);
    }
    __syncthreads();

    // --- softmax over 128 logits (warp 0): logits = (ssum/128)/TAU ---
    if (wid == 0) {
        const float scale = 1.f / (128.f * 0.25f);
        float sv[4], mx = -1e30f;
#pragma unroll
        for (int q = 0; q < 4; ++q) {
            sv[q] = sw[NODES + lane + 32 * q] * scale;
            mx = fmaxf(mx, sv[q]);
        }
#pragma unroll
        for (int o = 16; o; o >>= 1)
            mx = fmaxf(mx, __shfl_xor_sync(0xffffffffu, mx, o));
        float e[4], se = 0.f;
#pragma unroll
        for (int q = 0; q < 4; ++q) {
            e[q] = expf(sv[q] - mx);
            se += e[q];
        }
        se = warpsum(se);
        float inv = 1.f / se;
#pragma unroll
        for (int q = 0; q < 4; ++q) {
            float w_ = e[q] * inv;
            int i = lane + 32 * q;
            sw[2 * NODES + i] = w_;
            out[(size_t)NG * OUTD + (size_t)g * NODES + i] = w_;
        }
    }
    __syncthreads();

    // --- v[d] = sum_i w_i * z[i][d] ---
    if (tid < OUTD) {
        float a = 0.f;
#pragma unroll 4
        for (int i = 0; i < NODES; ++i)
            a = fmaf(sw[2 * NODES + i], saux[tid * ZSTR + i], a);
        out[(size_t)g * OUTD + tid] = a;
    }
}

}  // namespace lb

extern "C" void kernel_launch(void* const* d_in, const int* in_sizes, int n_in,
                              void* d_out, int out_size)
{
    (void)in_sizes; (void)n_in; (void)out_size;
    const float* H     = (const float*)d_in[0];
    // d_in[1] = batch_ptr (uniform graphs; unused)
    const float* W_in  = (const float*)d_in[2];
    const float* b_in  = (const float*)d_in[3];
    const float* g_in  = (const float*)d_in[4];
    const float* be_in = (const float*)d_in[5];
    const float* Wb    = (const float*)d_in[6];
    const float* bb    = (const float*)d_in[7];
    const float* gb    = (const float*)d_in[8];
    const float* betab = (const float*)d_in[9];
    const float* W_out = (const float*)d_in[10];
    const float* b_out = (const float*)d_in[11];
    const float* g_out = (const float*)d_in[12];
    const float* be_out= (const float*)d_in[13];
    float* out = (float*)d_out;

    cudaFuncSetAttribute(lb::fused_local_branch,
                         cudaFuncAttributeMaxDynamicSharedMemorySize,
                         lb::SMEM_BYTES);

    lb::fused_local_branch<<<lb::NG, lb::TPB, lb::SMEM_BYTES>>>(
        H, W_in, b_in, g_in, be_in, Wb, bb, gb, betab,
        W_out, b_out, g_out, be_out, out);
}